// round 3
// baseline (speedup 1.0000x reference)
#include <cuda_runtime.h>
#include <math.h>

// act: (4, 4096, 4096) fp32, GROUP_SIZE=32 -> 128 global group maxes.
#define DCOL    4096
#define NGROUP  128
#define NROWS   16384
#define NELEM   ((size_t)NROWS * (size_t)DCOL)   // 67,108,864
#define N4      (NELEM / 4)                      // 16,777,216 float4
#define RBLOCKS 296                              // reduce grid (2 per SM x 148)

// Scratch (__device__ globals: allocation-free rule).
// Every slot is written on every run -> no init kernel, no atomics, deterministic.
__device__ float g_part[RBLOCKS * NGROUP];
__device__ float g_scale[NGROUP];
__device__ float g_inv_scale[NGROUP];

// ---------------------------------------------------------------------------
// Phase 1: per-block group abs-max. Thread x owns float4-column x (group x>>3).
// 4 independent accumulators over 4 grid-strided rows -> MLP=4 per thread.
// ---------------------------------------------------------------------------
__global__ void __launch_bounds__(1024, 2)
mx_reduce_kernel(const float4* __restrict__ act4) {
    const int x = threadIdx.x;                  // 0..1023
    const int S = RBLOCKS;
    float m0 = 0.f, m1 = 0.f, m2 = 0.f, m3 = 0.f;
    int row = blockIdx.x;
    for (; row < NROWS - 3 * S; row += 4 * S) {
        float4 v0 = act4[(size_t)(row        ) * (DCOL / 4) + x];
        float4 v1 = act4[(size_t)(row +     S) * (DCOL / 4) + x];
        float4 v2 = act4[(size_t)(row + 2 * S) * (DCOL / 4) + x];
        float4 v3 = act4[(size_t)(row + 3 * S) * (DCOL / 4) + x];
        m0 = fmaxf(m0, fmaxf(fmaxf(fabsf(v0.x), fabsf(v0.y)), fmaxf(fabsf(v0.z), fabsf(v0.w))));
        m1 = fmaxf(m1, fmaxf(fmaxf(fabsf(v1.x), fabsf(v1.y)), fmaxf(fabsf(v1.z), fabsf(v1.w))));
        m2 = fmaxf(m2, fmaxf(fmaxf(fabsf(v2.x), fabsf(v2.y)), fmaxf(fabsf(v2.z), fabsf(v2.w))));
        m3 = fmaxf(m3, fmaxf(fmaxf(fabsf(v3.x), fabsf(v3.y)), fmaxf(fabsf(v3.z), fabsf(v3.w))));
    }
    for (; row < NROWS; row += S) {
        float4 v = act4[(size_t)row * (DCOL / 4) + x];
        m0 = fmaxf(m0, fmaxf(fmaxf(fabsf(v.x), fabsf(v.y)), fmaxf(fabsf(v.z), fabsf(v.w))));
    }
    float m = fmaxf(fmaxf(m0, m1), fmaxf(m2, m3));
    m = fmaxf(m, __shfl_xor_sync(0xffffffffu, m, 1));
    m = fmaxf(m, __shfl_xor_sync(0xffffffffu, m, 2));
    m = fmaxf(m, __shfl_xor_sync(0xffffffffu, m, 4));
    if ((x & 7) == 0)
        g_part[blockIdx.x * NGROUP + (x >> 3)] = m;   // non-atomic, all slots written
}

// ---------------------------------------------------------------------------
// Phase 2 (tiny): fold 296 partials per group; exps = floor(log2(max))
// (ilogbf exact for normals AND subnormals), scale = 2^exps.
// ---------------------------------------------------------------------------
__global__ void mx_finalize_kernel(float* __restrict__ exps_out) {
    int g = threadIdx.x;
    if (g >= NGROUP) return;
    float mx = 0.f;
    #pragma unroll 8
    for (int b = 0; b < RBLOCKS; b++)
        mx = fmaxf(mx, g_part[b * NGROUP + g]);
    float e = (mx > 0.f) ? (float)ilogbf(mx) : 0.f;
    float s = exp2f(e);
    exps_out[g]    = e;
    g_scale[g]     = s;
    g_inv_scale[g] = 1.f / s;    // exact (power of two)
}

// ---------------------------------------------------------------------------
// Phase 3: quantize. 4 float4 per thread (MLP=4), streaming loads/stores.
// All arithmetic exact (pow2 scale); rintf == round-half-even == jnp.round.
// ---------------------------------------------------------------------------
__device__ __forceinline__ float mx_quant1(float a, float s, float inv) {
    float r = fminf(fabsf(a) * inv, 1.0f);
    float m = rintf(r * 8.0f) * 0.125f;
    return copysignf(s * m, a);
}

__device__ __forceinline__ float4 mx_quant4(float4 v, float s, float inv) {
    float4 q;
    q.x = mx_quant1(v.x, s, inv);
    q.y = mx_quant1(v.y, s, inv);
    q.z = mx_quant1(v.z, s, inv);
    q.w = mx_quant1(v.w, s, inv);
    return q;
}

__global__ void __launch_bounds__(512, 4)
mx_quant_kernel(const float4* __restrict__ act4,
                float4* __restrict__ out4) {
    size_t base = (size_t)blockIdx.x * 2048 + threadIdx.x;   // 4 items, stride 512
    size_t i0 = base, i1 = base + 512, i2 = base + 1024, i3 = base + 1536;
    // issue all 4 loads first (MLP=4)
    float4 v0 = __ldcs(&act4[i0]);
    float4 v1 = __ldcs(&act4[i1]);
    float4 v2 = __ldcs(&act4[i2]);
    float4 v3 = __ldcs(&act4[i3]);
    int g0 = (int)(i0 & 1023u) >> 3;
    int g1 = (int)(i1 & 1023u) >> 3;
    int g2 = (int)(i2 & 1023u) >> 3;
    int g3 = (int)(i3 & 1023u) >> 3;
    float4 q0 = mx_quant4(v0, __ldg(&g_scale[g0]), __ldg(&g_inv_scale[g0]));
    float4 q1 = mx_quant4(v1, __ldg(&g_scale[g1]), __ldg(&g_inv_scale[g1]));
    float4 q2 = mx_quant4(v2, __ldg(&g_scale[g2]), __ldg(&g_inv_scale[g2]));
    float4 q3 = mx_quant4(v3, __ldg(&g_scale[g3]), __ldg(&g_inv_scale[g3]));
    __stcs(&out4[i0], q0);
    __stcs(&out4[i1], q1);
    __stcs(&out4[i2], q2);
    __stcs(&out4[i3], q3);
}

// ---------------------------------------------------------------------------
// Launch: reduce -> finalize -> quantize.
// Output layout: q (67,108,864 floats) followed by exps (128 floats).
// ---------------------------------------------------------------------------
extern "C" void kernel_launch(void* const* d_in, const int* in_sizes, int n_in,
                              void* d_out, int out_size) {
    const float4* act4 = (const float4*)d_in[0];
    float* out      = (float*)d_out;
    float* exps_out = out + ((size_t)out_size - NGROUP);

    mx_reduce_kernel<<<RBLOCKS, 1024>>>(act4);
    mx_finalize_kernel<<<1, 128>>>(exps_out);
    mx_quant_kernel<<<(unsigned)(N4 / 2048), 512>>>(act4, (float4*)out);
}